// round 4
// baseline (speedup 1.0000x reference)
#include <cuda_runtime.h>

#define B   32
#define C   512
#define HW  1024
#define T   1025
#define NH  8
#define CH  64
#define SCALE2 0.125f   // (1/64^{0.25})^2 = 1/8

// ---------------------------------------------------------------------------
// Scratch (allocation-free rules -> __device__ globals)
__device__ float g_x0 [B * C];          // mean-token input: mean + pos[:,0]
__device__ float g_q0 [B * C];          // scaled q at t=0: 0.125*(W_q x0 + b_q)
__device__ float g_k0 [B * C];          // W_k x0  (NO bias: constant dropped)
__device__ float g_qw [B * NH * C];     // folded query weight: q0s^T W_k
__device__ float g_p  [B * NH * T];     // logits
__device__ float g_ps [B * NH * HW];    // probs, shifted: [row][t-1]
__device__ float g_p0 [B * NH];         // prob at t=0
__device__ float g_y  [B * NH * C];     // prob-weighted xf sums
__device__ float g_a  [B * C];          // attn output (pre out-proj)

// Global software barrier state (sense-reversing; self-resetting across replays)
__device__ unsigned g_count = 0;
__device__ volatile unsigned g_sense = 0;

__device__ __forceinline__ float wred(float v) {
    #pragma unroll
    for (int o = 16; o; o >>= 1) v += __shfl_down_sync(0xffffffffu, v, o);
    return v;
}

// ---------------------------------------------------------------------------
__global__ void __launch_bounds__(256)
attn_pool_persistent(const float* __restrict__ x,
                     const float* __restrict__ pos,
                     const float* __restrict__ wqkv,
                     const float* __restrict__ bqkv,
                     const float* __restrict__ wc,
                     const float* __restrict__ bc,
                     float* __restrict__ out) {
    __shared__ float buf[8208];          // phase-shared scratch (32.8 KB)
    __shared__ unsigned s_sense;

    const int tid  = threadIdx.x;
    const int warp = tid >> 5, lane = tid & 31;
    const int bid  = blockIdx.x;
    const int NB   = gridDim.x;
    const int NW   = NB * 8;             // total warps
    const int gw   = bid * 8 + warp;     // global warp id

    if (tid == 0) s_sense = g_sense;     // stable between launches
    __syncthreads();

    // Sense-reversing grid barrier. All blocks co-resident (1 block/SM).
    auto gbar = [&]() {
        __syncthreads();
        if (tid == 0) {
            unsigned s = s_sense ^ 1u;
            s_sense = s;
            __threadfence();
            unsigned arrived = atomicAdd(&g_count, 1u);
            if (arrived == (unsigned)NB - 1u) {
                g_count = 0;
                __threadfence();
                g_sense = s;
            } else {
                while (g_sense != s) __nanosleep(64);
            }
            __threadfence();
        }
        __syncthreads();
    };

    // ---- Phase 1: spatial mean -> x0 = mean + pos[c,0] ---------------------
    for (int row = gw; row < B * C; row += NW) {
        const float4* p = (const float4*)(x + (size_t)row * HW);
        float s = 0.0f;
        #pragma unroll
        for (int k = 0; k < 8; k++) {
            float4 v = p[lane + 32 * k];
            s += v.x + v.y + v.z + v.w;
        }
        s = wred(s);
        if (lane == 0) {
            int c = row & (C - 1);
            g_x0[row] = s * (1.0f / HW) + pos[(size_t)c * T];
        }
    }
    gbar();

    // ---- Phase 2: q0s[b,o] and k0[b,o] (warp per output, 2*B*C items) ------
    for (int it = gw; it < 2 * B * C; it += NW) {
        int qk  = it >> 14;              // 0 = q, 1 = k
        int idx = it & (B * C - 1);
        int b = idx >> 9, o = idx & (C - 1);
        const float4* w  = (const float4*)(wqkv + (size_t)(qk * C + o) * C);
        const float4* xv = (const float4*)(g_x0 + (size_t)b * C);
        float acc = 0.0f;
        #pragma unroll
        for (int k = 0; k < 4; k++) {
            int i = lane + 32 * k;
            float4 a = w[i], d = xv[i];
            acc += a.x * d.x + a.y * d.y + a.z * d.z + a.w * d.w;
        }
        acc = wred(acc);
        if (lane == 0) {
            if (qk == 0) g_q0[idx] = SCALE2 * (acc + bqkv[o]);
            else         g_k0[idx] = acc;   // bias dropped (softmax shift-inv.)
        }
    }
    gbar();

    // ---- Phase 3: qw fold (thread per output) + logit0 (warp per (b,h)) ----
    for (int idx = bid * 256 + tid; idx < B * NH * C; idx += NB * 256) {
        int b = idx >> 12, rem = idx & 4095, h = rem >> 9, ci = rem & (C - 1);
        const float* wk = wqkv + (size_t)(C + h * CH) * C + ci;
        const float* q  = g_q0 + (size_t)b * C + h * CH;
        float acc = 0.0f;
        #pragma unroll 8
        for (int ch = 0; ch < CH; ch++) acc += q[ch] * wk[(size_t)ch * C];
        g_qw[idx] = acc;
    }
    for (int it = gw; it < B * NH; it += NW) {
        int b = it >> 3, h = it & 7;
        const float* q = g_q0 + (size_t)b * C + h * CH;
        const float* k = g_k0 + (size_t)b * C + h * CH;
        float acc = 0.0f;
        #pragma unroll
        for (int kk = 0; kk < 2; kk++) {
            int i = lane + 32 * kk;
            acc += q[i] * k[i];
        }
        acc = wred(acc);
        if (lane == 0) g_p[(size_t)it * T] = acc;
    }
    gbar();

    // ---- Phase 4: logits t=1..1024.  128 units of (b, 256-t chunk) ---------
    for (int u = bid; u < 128; u += NB) {
        int b = u >> 2;
        int tm1 = (u & 3) * 256 + tid;               // t-1 in 0..1023
        float* sqw  = buf;                           // [ci*8+h], 4096 floats
        float* tile = buf + 4096;                    // 2 x 8 x 256
        for (int i = tid; i < NH * C; i += 256) {
            int h = i >> 9, ci = i & (C - 1);
            sqw[ci * 8 + h] = g_qw[(size_t)b * NH * C + i];
        }
        const float* xb = x + (size_t)b * C * HW + tm1;
        const float* pb = pos + tm1 + 1;
        float v[8];
        #pragma unroll
        for (int r = 0; r < 8; r++)
            v[r] = xb[(size_t)r * HW] + pb[(size_t)r * T];
        float acc[8] = {0, 0, 0, 0, 0, 0, 0, 0};
        int bi = 0;
        for (int c0 = 0; c0 < C; c0 += 8) {
            float* tb = tile + bi * 2048;
            #pragma unroll
            for (int r = 0; r < 8; r++) tb[r * 256 + tid] = v[r];
            __syncthreads();
            if (c0 + 8 < C) {
                const float* xn = xb + (size_t)(c0 + 8) * HW;
                const float* pn = pb + (size_t)(c0 + 8) * T;
                #pragma unroll
                for (int r = 0; r < 8; r++)
                    v[r] = xn[(size_t)r * HW] + pn[(size_t)r * T];
            }
            #pragma unroll
            for (int r = 0; r < 8; r++) {
                float xv = tb[r * 256 + tid];
                const float4* w = (const float4*)&sqw[(c0 + r) * 8];
                float4 w0 = w[0], w1 = w[1];
                acc[0] += w0.x * xv; acc[1] += w0.y * xv;
                acc[2] += w0.z * xv; acc[3] += w0.w * xv;
                acc[4] += w1.x * xv; acc[5] += w1.y * xv;
                acc[6] += w1.z * xv; acc[7] += w1.w * xv;
            }
            bi ^= 1;
        }
        #pragma unroll
        for (int h = 0; h < 8; h++)
            g_p[((size_t)b * NH + h) * T + tm1 + 1] = acc[h];
        __syncthreads();
    }
    gbar();

    // ---- Phase 5: softmax over T per row; emit shifted probs ---------------
    for (int row = bid; row < B * NH; row += NB) {
        const float* p = g_p + (size_t)row * T;
        float v[5];
        #pragma unroll
        for (int k = 0; k < 5; k++) {
            int t = tid + k * 256;
            v[k] = (t < T) ? p[t] : -1e30f;
        }
        float m = v[0];
        #pragma unroll
        for (int k = 1; k < 5; k++) m = fmaxf(m, v[k]);
        #pragma unroll
        for (int o = 16; o; o >>= 1) m = fmaxf(m, __shfl_down_sync(0xffffffffu, m, o));
        if (lane == 0) buf[warp] = m;
        __syncthreads();
        float M = buf[0];
        #pragma unroll
        for (int w = 1; w < 8; w++) M = fmaxf(M, buf[w]);
        __syncthreads();
        float s = 0.0f;
        #pragma unroll
        for (int k = 0; k < 5; k++) { v[k] = __expf(v[k] - M); s += v[k]; }
        s = wred(s);
        if (lane == 0) buf[warp] = s;
        __syncthreads();
        float S = buf[0] + buf[1] + buf[2] + buf[3] + buf[4] + buf[5] + buf[6] + buf[7];
        float inv = 1.0f / S;
        #pragma unroll
        for (int k = 0; k < 5; k++) {
            int t = tid + k * 256;
            if (t == 0)     g_p0[row] = v[k] * inv;
            else if (t < T) g_ps[(size_t)row * HW + t - 1] = v[k] * inv;
        }
        __syncthreads();
    }
    gbar();

    // ---- Phase 6: y[b,h,ci] = sum_t p * xf.  Contiguous item chunks --------
    {
        const int NITEMS = B * (C / 8);              // 2048: (b, ci-group-of-8)
        int start = (int)(((long long)bid * NITEMS) / NB);
        int end   = (int)(((long long)(bid + 1) * NITEMS) / NB);
        int cur_b = -1;
        for (int it = start; it < end; it++) {
            int b = it >> 6, ci8 = it & 63;
            if (b != cur_b) {
                __syncthreads();
                const float4* src = (const float4*)(g_ps + (size_t)b * NH * HW);
                float4* dst = (float4*)buf;
                #pragma unroll
                for (int k = 0; k < 8; k++) dst[tid + 256 * k] = src[tid + 256 * k];
                if (tid < NH) buf[8192 + tid] = g_p0[b * NH + tid];
                __syncthreads();
                cur_b = b;
            }
            int ci = ci8 * 8 + warp;
            const float4* xr = (const float4*)(x + ((size_t)b * C + ci) * HW);
            const float*  pp = pos + (size_t)ci * T;
            float acc[8] = {0, 0, 0, 0, 0, 0, 0, 0};
            #pragma unroll
            for (int k = 0; k < 8; k++) {
                int i4 = lane + 32 * k;
                float4 xv = xr[i4];
                int tb = 4 * i4;
                float v0 = xv.x + pp[tb + 1];
                float v1 = xv.y + pp[tb + 2];
                float v2 = xv.z + pp[tb + 3];
                float v3 = xv.w + pp[tb + 4];
                #pragma unroll
                for (int h = 0; h < 8; h++) {
                    float4 pv = ((const float4*)buf)[h * (HW / 4) + i4];
                    acc[h] += pv.x * v0 + pv.y * v1 + pv.z * v2 + pv.w * v3;
                }
            }
            if (lane == 0) {
                float v = g_x0[(size_t)b * C + ci];
                #pragma unroll
                for (int h = 0; h < 8; h++) acc[h] += buf[8192 + h] * v;
            }
            #pragma unroll
            for (int h = 0; h < 8; h++) {
                float r = wred(acc[h]);
                if (lane == 0) g_y[((size_t)b * NH + h) * C + ci] = r;
            }
        }
    }
    gbar();

    // ---- Phase 7: attn[b,c] = b_v[c] + W_v[c,:] . y[b,c/64,:] --------------
    for (int it = gw; it < B * C; it += NW) {
        int b = it >> 9, c = it & (C - 1), h = c >> 6;
        const float4* w = (const float4*)(wqkv + (size_t)(2 * C + c) * C);
        const float4* y = (const float4*)(g_y + (size_t)b * NH * C + h * C);
        float acc = 0.0f;
        #pragma unroll
        for (int k = 0; k < 4; k++) {
            int i = lane + 32 * k;
            float4 a = w[i], d = y[i];
            acc += a.x * d.x + a.y * d.y + a.z * d.z + a.w * d.w;
        }
        acc = wred(acc);
        if (lane == 0) g_a[it] = acc + bqkv[2 * C + c];
    }
    gbar();

    // ---- Phase 8: out[b,o] = b_c[o] + W_c[o,:] . attn[b,:] -----------------
    for (int it = gw; it < B * C; it += NW) {
        int b = it >> 9, o = it & (C - 1);
        const float4* w = (const float4*)(wc + (size_t)o * C);
        const float4* a = (const float4*)(g_a + (size_t)b * C);
        float acc = 0.0f;
        #pragma unroll
        for (int k = 0; k < 4; k++) {
            int i = lane + 32 * k;
            float4 u = w[i], d = a[i];
            acc += u.x * d.x + u.y * d.y + u.z * d.z + u.w * d.w;
        }
        acc = wred(acc);
        if (lane == 0) out[it] = acc + bc[o];
    }
}

// ---------------------------------------------------------------------------
extern "C" void kernel_launch(void* const* d_in, const int* in_sizes, int n_in,
                              void* d_out, int out_size) {
    const float* x    = (const float*)d_in[0];
    const float* pos  = (const float*)d_in[1];
    const float* wqkv = (const float*)d_in[2];
    const float* bqkv = (const float*)d_in[3];
    const float* wc   = (const float*)d_in[4];
    const float* bc   = (const float*)d_in[5];
    float* out = (float*)d_out;

    int nsm = 0;
    cudaDeviceGetAttribute(&nsm, cudaDevAttrMultiProcessorCount, 0);
    if (nsm <= 0) nsm = 148;
    attn_pool_persistent<<<nsm, 256>>>(x, pos, wqkv, bqkv, wc, bc, out);
}

// round 5
// speedup vs baseline: 1.4718x; 1.4718x over previous
#include <cuda_runtime.h>

#define B   32
#define C   512
#define HW  1024
#define T   1025
#define NH  8
#define CH  64
#define SCALE2 0.125f   // (1/64^{0.25})^2 = 1/8

// ---------------------------------------------------------------------------
// Scratch (allocation-free rules -> __device__ globals)
__device__ float g_x0 [B * C];          // mean-token input: mean + pos[:,0]
__device__ float g_q0 [B * C];          // scaled q at t=0: 0.125*(W_q x0 + b_q)
__device__ float g_k0 [B * C];          // W_k x0  (bias dropped: softmax shift-inv)
__device__ float g_qw [B * NH * C];     // folded query weight: q0s^T W_k
__device__ float g_p  [B * NH * T];     // logits
__device__ float g_ps [B * NH * HW];    // probs, shifted: [row][t-1]
__device__ float g_p0 [B * NH];         // prob at t=0
__device__ float g_y  [B * NH * C];     // prob-weighted xf sums
__device__ float g_a  [B * C];          // attn output (pre out-proj)

__device__ unsigned g_count = 0;
__device__ volatile unsigned g_sense = 0;

__device__ __forceinline__ float wred(float v) {
    #pragma unroll
    for (int o = 16; o; o >>= 1) v += __shfl_down_sync(0xffffffffu, v, o);
    return v;
}

// ---------------------------------------------------------------------------
__global__ void __launch_bounds__(1024, 1)
attn_pool_persistent(const float* __restrict__ x,
                     const float* __restrict__ pos,
                     const float* __restrict__ wqkv,
                     const float* __restrict__ bqkv,
                     const float* __restrict__ wc,
                     const float* __restrict__ bc,
                     float* __restrict__ out) {
    __shared__ float buf[12288];         // 48 KB phase-shared scratch

    const int tid  = threadIdx.x;
    const int warp = tid >> 5, lane = tid & 31;
    const int bid  = blockIdx.x;
    const int NB   = gridDim.x;
    const int NW   = NB * 32;            // total warps
    const int gw   = bid * 32 + warp;    // global warp id

    unsigned sense = g_sense;            // per-thread barrier sense

    // Sense-reversing grid barrier (1 block/SM guaranteed -> co-resident).
    auto gbar = [&]() {
        __syncthreads();
        if (tid == 0) {
            unsigned s = sense ^ 1u;
            __threadfence();
            if (atomicAdd(&g_count, 1u) == (unsigned)NB - 1u) {
                g_count = 0;
                __threadfence();
                g_sense = s;
            } else {
                while (g_sense != s) __nanosleep(32);
            }
            __threadfence();
        }
        __syncthreads();
        sense ^= 1u;
    };

    // ---- Phase 1: spatial mean -> x0 = mean + pos[c,0].  Warp per row. -----
    for (int row = gw; row < B * C; row += NW) {
        const float4* p = (const float4*)(x + (size_t)row * HW);
        float s = 0.0f;
        #pragma unroll
        for (int k = 0; k < 8; k++) {
            float4 v = p[lane + 32 * k];
            s += v.x + v.y + v.z + v.w;
        }
        s = wred(s);
        if (lane == 0)
            g_x0[row] = s * (1.0f / HW) + pos[(size_t)(row & (C - 1)) * T];
    }
    gbar();

    // ---- Phase 2: q0s & k0.  Warp per (qk, o, b-group-of-8); w row cached. -
    for (int it = gw; it < 2 * C * 4; it += NW) {
        int qk = it >> 11, rem = it & 2047;
        int o = rem >> 2, bg = rem & 3;
        const float4* w = (const float4*)(wqkv + (size_t)(qk * C + o) * C);
        float4 wr[4];
        #pragma unroll
        for (int k = 0; k < 4; k++) wr[k] = w[lane + 32 * k];
        float bq = bqkv[o];
        #pragma unroll
        for (int j = 0; j < 8; j++) {
            int b = bg * 8 + j;
            const float4* xv = (const float4*)(g_x0 + (size_t)b * C);
            float acc = 0.0f;
            #pragma unroll
            for (int k = 0; k < 4; k++) {
                float4 d = xv[lane + 32 * k];
                acc += wr[k].x * d.x + wr[k].y * d.y + wr[k].z * d.z + wr[k].w * d.w;
            }
            acc = wred(acc);
            if (lane == 0) {
                if (qk == 0) g_q0[b * C + o] = SCALE2 * (acc + bq);
                else         g_k0[b * C + o] = acc;
            }
        }
    }
    gbar();

    // ---- Phase 3: qw fold (thread/output) + logit0 (warp per (b,h)) --------
    for (int idx = bid * 1024 + tid; idx < B * NH * C; idx += NB * 1024) {
        int b = idx >> 12, rem = idx & 4095, h = rem >> 9, ci = rem & (C - 1);
        const float* wk = wqkv + (size_t)(C + h * CH) * C + ci;
        const float* q  = g_q0 + (size_t)b * C + h * CH;
        float acc = 0.0f;
        #pragma unroll 8
        for (int ch = 0; ch < CH; ch++) acc += q[ch] * wk[(size_t)ch * C];
        g_qw[idx] = acc;
    }
    for (int it = gw; it < B * NH; it += NW) {
        int b = it >> 3, h = it & 7;
        const float* q = g_q0 + (size_t)b * C + h * CH;
        const float* k = g_k0 + (size_t)b * C + h * CH;
        float acc = q[lane] * k[lane] + q[lane + 32] * k[lane + 32];
        acc = wred(acc);
        if (lane == 0) g_p[(size_t)it * T] = acc;
    }
    gbar();

    // ---- Phase 4: logits t=1..1024.  Unit = (b, 128-t chunk); 256 units. ---
    // 8 quads of 128 threads each own a 64-channel slab; reduce via smem.
    for (int u = bid; u < 256; u += NB) {
        int b  = u >> 3;
        int t0 = (u & 7) * 128;
        int tl = tid & 127, quad = tid >> 7;
        for (int i = tid; i < NH * C; i += 1024) {
            int h = i >> 9, ci = i & (C - 1);
            buf[ci * 8 + h] = g_qw[(size_t)b * NH * C + i];
        }
        __syncthreads();

        const float* xb = x + (size_t)b * C * HW + (t0 + tl);
        const float* pb = pos + (t0 + tl) + 1;
        float acc[8] = {0, 0, 0, 0, 0, 0, 0, 0};
        int ci0 = quad * 64;
        #pragma unroll 4
        for (int cc = 0; cc < 64; cc++) {
            int ci = ci0 + cc;
            float xv = xb[(size_t)ci * HW] + pb[(size_t)ci * T];
            const float4* wv = (const float4*)&buf[ci * 8];
            float4 w0 = wv[0], w1 = wv[1];
            acc[0] += w0.x * xv; acc[1] += w0.y * xv;
            acc[2] += w0.z * xv; acc[3] += w0.w * xv;
            acc[4] += w1.x * xv; acc[5] += w1.y * xv;
            acc[6] += w1.z * xv; acc[7] += w1.w * xv;
        }
        float* red = buf + 4096;
        #pragma unroll
        for (int h = 0; h < 8; h++) red[tl * 64 + quad * 8 + h] = acc[h];
        __syncthreads();
        {
            int tl2 = tid >> 3, h2 = tid & 7;
            float s = 0.0f;
            #pragma unroll
            for (int q = 0; q < 8; q++) s += red[tl2 * 64 + q * 8 + h2];
            g_p[((size_t)b * NH + h2) * T + t0 + tl2 + 1] = s;
        }
        __syncthreads();
    }
    gbar();

    // ---- Phase 5: softmax per row (block per row); emit shifted probs ------
    for (int row = bid; row < B * NH; row += NB) {
        const float* p = g_p + (size_t)row * T;
        float v0 = p[tid];
        float v1 = (tid == 0) ? p[1024] : -1e30f;
        float m = fmaxf(v0, v1);
        #pragma unroll
        for (int o = 16; o; o >>= 1) m = fmaxf(m, __shfl_down_sync(0xffffffffu, m, o));
        if (lane == 0) buf[warp] = m;
        __syncthreads();
        float M = buf[0];
        #pragma unroll
        for (int w = 1; w < 32; w++) M = fmaxf(M, buf[w]);
        __syncthreads();
        float e0 = __expf(v0 - M);
        float e1 = (tid == 0) ? __expf(v1 - M) : 0.0f;
        float s = wred(e0 + e1);
        if (lane == 0) buf[warp] = s;
        __syncthreads();
        float S = 0.0f;
        #pragma unroll
        for (int w = 0; w < 32; w++) S += buf[w];
        float inv = 1.0f / S;
        if (tid == 0) {
            g_p0[row] = e0 * inv;
            g_ps[(size_t)row * HW + 1023] = e1 * inv;
        } else {
            g_ps[(size_t)row * HW + tid - 1] = e0 * inv;
        }
        __syncthreads();
    }
    gbar();

    // ---- Phase 6: y[b,h,ci] = sum_t p*xf.  Warp per ci; probs staged. ------
    {
        const int NIT = B * (C / 32);    // 512 units of (b, ci-group-of-32)
        int start = (int)(((long long)bid * NIT) / NB);
        int end   = (int)(((long long)(bid + 1) * NIT) / NB);
        int cur_b = -1;
        for (int it = start; it < end; it++) {
            int b = it >> 4, cig = it & 15;
            if (b != cur_b) {
                __syncthreads();
                const float4* src = (const float4*)(g_ps + (size_t)b * NH * HW);
                float4* dst = (float4*)buf;
                #pragma unroll
                for (int k = 0; k < 2; k++) dst[tid + 1024 * k] = src[tid + 1024 * k];
                if (tid < NH) buf[8192 + tid] = g_p0[b * NH + tid];
                __syncthreads();
                cur_b = b;
            }
            int ci = cig * 32 + warp;
            const float4* xr = (const float4*)(x + ((size_t)b * C + ci) * HW);
            const float*  pp = pos + (size_t)ci * T;
            float acc[8] = {0, 0, 0, 0, 0, 0, 0, 0};
            #pragma unroll
            for (int k = 0; k < 8; k++) {
                int i4 = lane + 32 * k;
                float4 xv = xr[i4];
                int tb = 4 * i4;
                float v0 = xv.x + pp[tb + 1];
                float v1 = xv.y + pp[tb + 2];
                float v2 = xv.z + pp[tb + 3];
                float v3 = xv.w + pp[tb + 4];
                #pragma unroll
                for (int h = 0; h < 8; h++) {
                    float4 pv = ((const float4*)buf)[h * (HW / 4) + i4];
                    acc[h] += pv.x * v0 + pv.y * v1 + pv.z * v2 + pv.w * v3;
                }
            }
            if (lane == 0) {
                float v = g_x0[(size_t)b * C + ci];
                #pragma unroll
                for (int h = 0; h < 8; h++) acc[h] += buf[8192 + h] * v;
            }
            #pragma unroll
            for (int h = 0; h < 8; h++) {
                float r = wred(acc[h]);
                if (lane == 0) g_y[((size_t)b * NH + h) * C + ci] = r;
            }
        }
    }
    gbar();

    // ---- Phase 7: attn = b_v + W_v . y.  Warp per (c, b-group-of-8). -------
    for (int it = gw; it < C * 4; it += NW) {
        int c = it >> 2, bg = it & 3, h = c >> 6;
        const float4* w = (const float4*)(wqkv + (size_t)(2 * C + c) * C);
        float4 wr[4];
        #pragma unroll
        for (int k = 0; k < 4; k++) wr[k] = w[lane + 32 * k];
        float bv = bqkv[2 * C + c];
        #pragma unroll
        for (int j = 0; j < 8; j++) {
            int b = bg * 8 + j;
            const float4* y = (const float4*)(g_y + ((size_t)b * NH + h) * C);
            float acc = 0.0f;
            #pragma unroll
            for (int k = 0; k < 4; k++) {
                float4 d = y[lane + 32 * k];
                acc += wr[k].x * d.x + wr[k].y * d.y + wr[k].z * d.z + wr[k].w * d.w;
            }
            acc = wred(acc);
            if (lane == 0) g_a[b * C + c] = acc + bv;
        }
    }
    gbar();

    // ---- Phase 8: out = b_c + W_c . attn.  Warp per (o, b-group-of-8). -----
    for (int it = gw; it < C * 4; it += NW) {
        int o = it >> 2, bg = it & 3;
        const float4* w = (const float4*)(wc + (size_t)o * C);
        float4 wr[4];
        #pragma unroll
        for (int k = 0; k < 4; k++) wr[k] = w[lane + 32 * k];
        float bo = bc[o];
        #pragma unroll
        for (int j = 0; j < 8; j++) {
            int b = bg * 8 + j;
            const float4* a = (const float4*)(g_a + (size_t)b * C);
            float acc = 0.0f;
            #pragma unroll
            for (int k = 0; k < 4; k++) {
                float4 d = a[lane + 32 * k];
                acc += wr[k].x * d.x + wr[k].y * d.y + wr[k].z * d.z + wr[k].w * d.w;
            }
            acc = wred(acc);
            if (lane == 0) out[b * C + o] = acc + bo;
        }
    }
}

// ---------------------------------------------------------------------------
extern "C" void kernel_launch(void* const* d_in, const int* in_sizes, int n_in,
                              void* d_out, int out_size) {
    const float* x    = (const float*)d_in[0];
    const float* pos  = (const float*)d_in[1];
    const float* wqkv = (const float*)d_in[2];
    const float* bqkv = (const float*)d_in[3];
    const float* wc   = (const float*)d_in[4];
    const float* bc   = (const float*)d_in[5];
    float* out = (float*)d_out;

    int nsm = 0;
    cudaDeviceGetAttribute(&nsm, cudaDevAttrMultiProcessorCount, 0);
    if (nsm <= 0) nsm = 148;
    attn_pool_persistent<<<nsm, 1024>>>(x, pos, wqkv, bqkv, wc, bc, out);
}

// round 6
// speedup vs baseline: 1.8227x; 1.2384x over previous
#include <cuda_runtime.h>

#define B   32
#define C   512
#define HW  1024
#define T   1025
#define NH  8
#define CH  64
#define SCALE2 0.125f   // (1/64^{0.25})^2 = 1/8

// ---------------------------------------------------------------------------
// Scratch (allocation-free rules -> __device__ globals)
__device__ float g_x0  [B * C];         // mean-token input: mean + pos[:,0]
__device__ float g_q0  [B * C];         // scaled q at t=0
__device__ float g_k0  [B * C];         // W_k x0 (bias dropped: softmax shift-inv)
__device__ float g_qw  [B * NH * C];    // folded query weight: q0s^T W_k
__device__ float g_p   [B * NH * T];    // logits
__device__ float g_ps  [B * NH * HW];   // probs, shifted: [row][t-1]
__device__ float g_p0  [B * NH];        // prob at t=0
__device__ float g_y   [B * NH * C];    // prob-weighted xf sums
__device__ float g_a   [B * C];         // attn output (pre out-proj)
__device__ float g_poss[C * HW];        // pos shifted: [c][t-1] = pos[c][t]

__device__ unsigned g_count = 0;
__device__ volatile unsigned g_sense = 0;

__device__ __forceinline__ float wred(float v) {
    #pragma unroll
    for (int o = 16; o; o >>= 1) v += __shfl_down_sync(0xffffffffu, v, o);
    return v;
}

// ---------------------------------------------------------------------------
__global__ void __launch_bounds__(1024, 1)
attn_pool_persistent(const float* __restrict__ x,
                     const float* __restrict__ pos,
                     const float* __restrict__ wqkv,
                     const float* __restrict__ bqkv,
                     const float* __restrict__ wc,
                     const float* __restrict__ bc,
                     float* __restrict__ out) {
    __shared__ float buf[12288];         // 48 KB phase-shared scratch

    const int tid  = threadIdx.x;
    const int warp = tid >> 5, lane = tid & 31;
    const int bid  = blockIdx.x;
    const int NB   = gridDim.x;
    const int NW   = NB * 32;
    const int gw   = bid * 32 + warp;

    unsigned sense = g_sense;

    auto gbar = [&]() {
        __syncthreads();
        if (tid == 0) {
            unsigned s = sense ^ 1u;
            __threadfence();
            if (atomicAdd(&g_count, 1u) == (unsigned)NB - 1u) {
                g_count = 0;
                __threadfence();
                g_sense = s;
            } else {
                while (g_sense != s) __nanosleep(32);
            }
            __threadfence();
        }
        __syncthreads();
        sense ^= 1u;
    };

    // ---- Phase 1: spatial mean -> x0; build shifted pos table --------------
    for (int row = gw; row < B * C; row += NW) {
        const float4* p = (const float4*)(x + (size_t)row * HW);
        float s = 0.0f;
        #pragma unroll
        for (int k = 0; k < 8; k++) {
            float4 v = p[lane + 32 * k];
            s += v.x + v.y + v.z + v.w;
        }
        s = wred(s);
        if (lane == 0)
            g_x0[row] = s * (1.0f / HW) + pos[(size_t)(row & (C - 1)) * T];
    }
    for (int i = bid * 1024 + tid; i < C * HW; i += NB * 1024) {
        int c = i >> 10, j = i & 1023;
        g_poss[i] = pos[(size_t)c * T + j + 1];
    }
    gbar();

    // ---- Phase 2: q0s & k0.  Warp per (qk, o, b-group-of-8). ---------------
    for (int it = gw; it < 2 * C * 4; it += NW) {
        int qk = it >> 11, rem = it & 2047;
        int o = rem >> 2, bg = rem & 3;
        const float4* w = (const float4*)(wqkv + (size_t)(qk * C + o) * C);
        float4 wr[4];
        #pragma unroll
        for (int k = 0; k < 4; k++) wr[k] = w[lane + 32 * k];
        float bq = bqkv[o];
        #pragma unroll
        for (int j = 0; j < 8; j++) {
            int b = bg * 8 + j;
            const float4* xv = (const float4*)(g_x0 + (size_t)b * C);
            float acc = 0.0f;
            #pragma unroll
            for (int k = 0; k < 4; k++) {
                float4 d = xv[lane + 32 * k];
                acc += wr[k].x * d.x + wr[k].y * d.y + wr[k].z * d.z + wr[k].w * d.w;
            }
            acc = wred(acc);
            if (lane == 0) {
                if (qk == 0) g_q0[b * C + o] = SCALE2 * (acc + bq);
                else         g_k0[b * C + o] = acc;
            }
        }
    }
    gbar();

    // ---- Phase 3: qw fold (thread/output) + logit0 (warp per (b,h)) --------
    for (int idx = bid * 1024 + tid; idx < B * NH * C; idx += NB * 1024) {
        int b = idx >> 12, rem = idx & 4095, h = rem >> 9, ci = rem & (C - 1);
        const float* wk = wqkv + (size_t)(C + h * CH) * C + ci;
        const float* q  = g_q0 + (size_t)b * C + h * CH;
        float acc = 0.0f;
        #pragma unroll 8
        for (int ch = 0; ch < CH; ch++) acc += q[ch] * wk[(size_t)ch * C];
        g_qw[idx] = acc;
    }
    for (int it = gw; it < B * NH; it += NW) {
        int b = it >> 3, h = it & 7;
        const float* q = g_q0 + (size_t)b * C + h * CH;
        const float* k = g_k0 + (size_t)b * C + h * CH;
        float acc = q[lane] * k[lane] + q[lane + 32] * k[lane + 32];
        acc = wred(acc);
        if (lane == 0) g_p[(size_t)it * T] = acc;
    }
    gbar();

    // ---- Phase 4: logits t=1..1024.  Unit=(b, 256-t chunk); 128 units. -----
    // 8 slabs x 128 threads; thread owns 2 consecutive t (float2 loads).
    for (int u = bid; u < B * 4; u += NB) {
        int b  = u >> 2;
        int t0 = (u & 3) * 256;
        int tl = tid & 127, slab = tid >> 7;
        for (int i = tid; i < NH * C; i += 1024) {
            int h = i >> 9, ci = i & (C - 1);
            buf[ci * 8 + h] = g_qw[(size_t)b * NH * C + i];
        }
        __syncthreads();

        int t = t0 + 2 * tl;
        const float2* xb = (const float2*)(x + (size_t)b * C * HW + t);
        const float2* pb = (const float2*)(g_poss + t);
        float acc[16];
        #pragma unroll
        for (int i = 0; i < 16; i++) acc[i] = 0.0f;
        int ci0 = slab * 64;
        #pragma unroll 4
        for (int cc = 0; cc < 64; cc++) {
            int ci = ci0 + cc;
            float2 xv = xb[(size_t)ci * (HW / 2)];
            float2 pv = pb[(size_t)ci * (HW / 2)];
            float v0 = xv.x + pv.x, v1 = xv.y + pv.y;
            const float4* wv = (const float4*)&buf[ci * 8];
            float4 w0 = wv[0], w1 = wv[1];
            acc[0]  += w0.x * v0; acc[1]  += w0.x * v1;
            acc[2]  += w0.y * v0; acc[3]  += w0.y * v1;
            acc[4]  += w0.z * v0; acc[5]  += w0.z * v1;
            acc[6]  += w0.w * v0; acc[7]  += w0.w * v1;
            acc[8]  += w1.x * v0; acc[9]  += w1.x * v1;
            acc[10] += w1.y * v0; acc[11] += w1.y * v1;
            acc[12] += w1.z * v0; acc[13] += w1.z * v1;
            acc[14] += w1.w * v0; acc[15] += w1.w * v1;
        }
        float* red = buf + 4096;                 // 8192 floats
        #pragma unroll
        for (int par = 0; par < 2; par++) {
            __syncthreads();
            #pragma unroll
            for (int h = 0; h < 8; h++)
                red[tl * 64 + slab * 8 + h] = acc[h * 2 + par];
            __syncthreads();
            int tl2 = tid >> 3, h2 = tid & 7;    // 1024 (t,h) pairs
            float s = 0.0f;
            #pragma unroll
            for (int q = 0; q < 8; q++) s += red[tl2 * 64 + q * 8 + h2];
            g_p[((size_t)b * NH + h2) * T + t0 + 2 * tl2 + par + 1] = s;
        }
        __syncthreads();
    }
    gbar();

    // ---- Phase 5: softmax per row; emit shifted probs ----------------------
    for (int row = bid; row < B * NH; row += NB) {
        const float* p = g_p + (size_t)row * T;
        float v0 = p[tid];
        float v1 = (tid == 0) ? p[1024] : -1e30f;
        float m = fmaxf(v0, v1);
        #pragma unroll
        for (int o = 16; o; o >>= 1) m = fmaxf(m, __shfl_down_sync(0xffffffffu, m, o));
        if (lane == 0) buf[warp] = m;
        __syncthreads();
        float M = buf[0];
        #pragma unroll
        for (int w = 1; w < 32; w++) M = fmaxf(M, buf[w]);
        __syncthreads();
        float e0 = __expf(v0 - M);
        float e1 = (tid == 0) ? __expf(v1 - M) : 0.0f;
        float s = wred(e0 + e1);
        if (lane == 0) buf[warp] = s;
        __syncthreads();
        float S = 0.0f;
        #pragma unroll
        for (int w = 0; w < 32; w++) S += buf[w];
        float inv = 1.0f / S;
        if (tid == 0) {
            g_p0[row] = e0 * inv;
            g_ps[(size_t)row * HW + 1023] = e1 * inv;
        } else {
            g_ps[(size_t)row * HW + tid - 1] = e0 * inv;
        }
        __syncthreads();
    }
    gbar();

    // ---- Phase 6: y = p . xf.  Warp owns 2 ci; probs staged in smem. -------
    {
        const int NIT = B * 8;               // (b, ci-group-of-64)
        int start = (int)(((long long)bid * NIT) / NB);
        int end   = (int)(((long long)(bid + 1) * NIT) / NB);
        int cur_b = -1;
        for (int it = start; it < end; it++) {
            int b = it >> 3, cig = it & 7;
            if (b != cur_b) {
                __syncthreads();
                const float4* src = (const float4*)(g_ps + (size_t)b * NH * HW);
                float4* dst = (float4*)buf;
                dst[tid] = src[tid];
                dst[tid + 1024] = src[tid + 1024];
                if (tid < NH) buf[8192 + tid] = g_p0[b * NH + tid];
                __syncthreads();
                cur_b = b;
            }
            int ci0 = cig * 64 + warp * 2;
            const float4* xr0 = (const float4*)(x + ((size_t)b * C + ci0) * HW);
            const float4* xr1 = xr0 + (HW / 4);
            const float4* pr0 = (const float4*)(g_poss + (size_t)ci0 * HW);
            const float4* pr1 = pr0 + (HW / 4);
            float acc0[8], acc1[8];
            #pragma unroll
            for (int h = 0; h < 8; h++) { acc0[h] = 0.0f; acc1[h] = 0.0f; }
            #pragma unroll
            for (int k = 0; k < 8; k++) {
                int i4 = lane + 32 * k;
                float4 xa = xr0[i4], pa = pr0[i4];
                float4 xc = xr1[i4], pc = pr1[i4];
                float a0 = xa.x + pa.x, a1 = xa.y + pa.y;
                float a2 = xa.z + pa.z, a3 = xa.w + pa.w;
                float c0 = xc.x + pc.x, c1 = xc.y + pc.y;
                float c2 = xc.z + pc.z, c3 = xc.w + pc.w;
                #pragma unroll
                for (int h = 0; h < 8; h++) {
                    float4 pv = ((const float4*)buf)[h * (HW / 4) + i4];
                    acc0[h] += pv.x * a0 + pv.y * a1 + pv.z * a2 + pv.w * a3;
                    acc1[h] += pv.x * c0 + pv.y * c1 + pv.z * c2 + pv.w * c3;
                }
            }
            if (lane == 0) {
                float va = g_x0[(size_t)b * C + ci0];
                float vc = g_x0[(size_t)b * C + ci0 + 1];
                #pragma unroll
                for (int h = 0; h < 8; h++) {
                    acc0[h] += buf[8192 + h] * va;
                    acc1[h] += buf[8192 + h] * vc;
                }
            }
            #pragma unroll
            for (int h = 0; h < 8; h++) {
                float r0 = wred(acc0[h]);
                float r1 = wred(acc1[h]);
                if (lane == 0) {
                    g_y[((size_t)b * NH + h) * C + ci0]     = r0;
                    g_y[((size_t)b * NH + h) * C + ci0 + 1] = r1;
                }
            }
        }
    }
    gbar();

    // ---- Phase 7: attn = b_v + W_v . y.  Warp per (c, b-group-of-8). -------
    for (int it = gw; it < C * 4; it += NW) {
        int c = it >> 2, bg = it & 3, h = c >> 6;
        const float4* w = (const float4*)(wqkv + (size_t)(2 * C + c) * C);
        float4 wr[4];
        #pragma unroll
        for (int k = 0; k < 4; k++) wr[k] = w[lane + 32 * k];
        float bv = bqkv[2 * C + c];
        #pragma unroll
        for (int j = 0; j < 8; j++) {
            int b = bg * 8 + j;
            const float4* y = (const float4*)(g_y + ((size_t)b * NH + h) * C);
            float acc = 0.0f;
            #pragma unroll
            for (int k = 0; k < 4; k++) {
                float4 d = y[lane + 32 * k];
                acc += wr[k].x * d.x + wr[k].y * d.y + wr[k].z * d.z + wr[k].w * d.w;
            }
            acc = wred(acc);
            if (lane == 0) g_a[b * C + c] = acc + bv;
        }
    }
    gbar();

    // ---- Phase 8: out = b_c + W_c . attn.  Warp per (o, b-group-of-8). -----
    for (int it = gw; it < C * 4; it += NW) {
        int o = it >> 2, bg = it & 3;
        const float4* w = (const float4*)(wc + (size_t)o * C);
        float4 wr[4];
        #pragma unroll
        for (int k = 0; k < 4; k++) wr[k] = w[lane + 32 * k];
        float bo = bc[o];
        #pragma unroll
        for (int j = 0; j < 8; j++) {
            int b = bg * 8 + j;
            const float4* a = (const float4*)(g_a + (size_t)b * C);
            float acc = 0.0f;
            #pragma unroll
            for (int k = 0; k < 4; k++) {
                float4 d = a[lane + 32 * k];
                acc += wr[k].x * d.x + wr[k].y * d.y + wr[k].z * d.z + wr[k].w * d.w;
            }
            acc = wred(acc);
            if (lane == 0) out[b * C + o] = acc + bo;
        }
    }
}

// ---------------------------------------------------------------------------
extern "C" void kernel_launch(void* const* d_in, const int* in_sizes, int n_in,
                              void* d_out, int out_size) {
    const float* x    = (const float*)d_in[0];
    const float* pos  = (const float*)d_in[1];
    const float* wqkv = (const float*)d_in[2];
    const float* bqkv = (const float*)d_in[3];
    const float* wc   = (const float*)d_in[4];
    const float* bc   = (const float*)d_in[5];
    float* out = (float*)d_out;

    int nsm = 0;
    cudaDeviceGetAttribute(&nsm, cudaDevAttrMultiProcessorCount, 0);
    if (nsm <= 0) nsm = 148;
    attn_pool_persistent<<<nsm, 1024>>>(x, pos, wqkv, bqkv, wc, bc, out);
}

// round 7
// speedup vs baseline: 1.9487x; 1.0692x over previous
#include <cuda_runtime.h>

#define B   32
#define C   512
#define HW  1024
#define T   1025
#define NH  8
#define CH  64
#define SCALE2 0.125f   // (1/64^{0.25})^2 = 1/8

typedef unsigned long long u64;

// ---------------------------------------------------------------------------
// Scratch (allocation-free rules -> __device__ globals)
__device__ float g_x0  [B * C];
__device__ float g_q0  [B * C];
__device__ float g_k0  [B * C];
__device__ float g_qw  [B * NH * C];
__device__ float g_p   [B * NH * T];
__device__ float g_ps  [B * NH * HW];   // probs, shifted: [b][h][t-1]
__device__ float g_p0  [B * NH];
__device__ float g_y   [B * NH * C];
__device__ float g_a   [B * C];
__device__ float g_poss[C * HW];        // pos shifted: [c][t-1]

__device__ unsigned g_count = 0;
__device__ volatile unsigned g_sense = 0;

__device__ __forceinline__ float wred(float v) {
    #pragma unroll
    for (int o = 16; o; o >>= 1) v += __shfl_down_sync(0xffffffffu, v, o);
    return v;
}

// ---- packed f32x2 helpers (Blackwell FFMA2 path, PTX-only) ----------------
__device__ __forceinline__ u64 pack2(float lo, float hi) {
    u64 r; asm("mov.b64 %0, {%1, %2};" : "=l"(r) : "f"(lo), "f"(hi)); return r;
}
__device__ __forceinline__ u64 add2(u64 a, u64 b) {
    u64 r; asm("add.rn.f32x2 %0, %1, %2;" : "=l"(r) : "l"(a), "l"(b)); return r;
}
__device__ __forceinline__ void fma2(u64& d, u64 a, u64 b) {
    asm("fma.rn.f32x2 %0, %1, %2, %0;" : "+l"(d) : "l"(a), "l"(b));
}
__device__ __forceinline__ float2 unpack2(u64 v) {
    float2 f; asm("mov.b64 {%0, %1}, %2;" : "=f"(f.x), "=f"(f.y) : "l"(v)); return f;
}

// ---------------------------------------------------------------------------
__global__ void __launch_bounds__(1024, 1)
attn_pool_persistent(const float* __restrict__ x,
                     const float* __restrict__ pos,
                     const float* __restrict__ wqkv,
                     const float* __restrict__ bqkv,
                     const float* __restrict__ wc,
                     const float* __restrict__ bc,
                     float* __restrict__ out) {
    __shared__ float buf[12288];         // 48 KB phase-shared scratch

    const int tid  = threadIdx.x;
    const int warp = tid >> 5, lane = tid & 31;
    const int bid  = blockIdx.x;
    const int NB   = gridDim.x;
    const int NW   = NB * 32;
    const int gw   = bid * 32 + warp;

    unsigned sense = g_sense;

    auto gbar = [&]() {
        __syncthreads();
        if (tid == 0) {
            unsigned s = sense ^ 1u;
            __threadfence();
            if (atomicAdd(&g_count, 1u) == (unsigned)NB - 1u) {
                g_count = 0;
                __threadfence();
                g_sense = s;
            } else {
                while (g_sense != s) { }
            }
            __threadfence();
        }
        __syncthreads();
        sense ^= 1u;
    };

    // ---- Phase 1: spatial mean -> x0; build shifted pos table --------------
    for (int row = gw; row < B * C; row += NW) {
        const float4* p = (const float4*)(x + (size_t)row * HW);
        float s = 0.0f;
        #pragma unroll
        for (int k = 0; k < 8; k++) {
            float4 v = p[lane + 32 * k];
            s += v.x + v.y + v.z + v.w;
        }
        s = wred(s);
        if (lane == 0)
            g_x0[row] = s * (1.0f / HW) + pos[(size_t)(row & (C - 1)) * T];
    }
    for (int i = bid * 1024 + tid; i < C * HW; i += NB * 1024) {
        int c = i >> 10, j = i & 1023;
        g_poss[i] = pos[(size_t)c * T + j + 1];
    }
    gbar();

    // ---- Phase 2: q0s & k0.  Warp per (qk, o, b-group-of-8). ---------------
    for (int it = gw; it < 2 * C * 4; it += NW) {
        int qk = it >> 11, rem = it & 2047;
        int o = rem >> 2, bg = rem & 3;
        const float4* w = (const float4*)(wqkv + (size_t)(qk * C + o) * C);
        float4 wr[4];
        #pragma unroll
        for (int k = 0; k < 4; k++) wr[k] = w[lane + 32 * k];
        float bq = bqkv[o];
        #pragma unroll
        for (int j = 0; j < 8; j++) {
            int b = bg * 8 + j;
            const float4* xv = (const float4*)(g_x0 + (size_t)b * C);
            float acc = 0.0f;
            #pragma unroll
            for (int k = 0; k < 4; k++) {
                float4 d = xv[lane + 32 * k];
                acc += wr[k].x * d.x + wr[k].y * d.y + wr[k].z * d.z + wr[k].w * d.w;
            }
            acc = wred(acc);
            if (lane == 0) {
                if (qk == 0) g_q0[b * C + o] = SCALE2 * (acc + bq);
                else         g_k0[b * C + o] = acc;
            }
        }
    }
    gbar();

    // ---- Phase 3: qw fold (thread/output) + logit0 (warp per (b,h)) --------
    for (int idx = bid * 1024 + tid; idx < B * NH * C; idx += NB * 1024) {
        int b = idx >> 12, rem = idx & 4095, h = rem >> 9, ci = rem & (C - 1);
        const float* wk = wqkv + (size_t)(C + h * CH) * C + ci;
        const float* q  = g_q0 + (size_t)b * C + h * CH;
        float acc = 0.0f;
        #pragma unroll 8
        for (int ch = 0; ch < CH; ch++) acc += q[ch] * wk[(size_t)ch * C];
        g_qw[idx] = acc;
    }
    for (int it = gw; it < B * NH; it += NW) {
        int b = it >> 3, h = it & 7;
        const float* q = g_q0 + (size_t)b * C + h * CH;
        const float* k = g_k0 + (size_t)b * C + h * CH;
        float acc = q[lane] * k[lane] + q[lane + 32] * k[lane + 32];
        acc = wred(acc);
        if (lane == 0) g_p[(size_t)it * T] = acc;
    }
    gbar();

    // ---- Phase 4: logits t=1..1024.  Unit=(b, 256-t chunk); 128 units. -----
    // 8 slabs x 128 threads; thread owns 2 t.  FFMA2 over h-pairs.
    for (int u = bid; u < B * 4; u += NB) {
        int b  = u >> 2;
        int t0 = (u & 3) * 256;
        int tl = tid & 127, slab = tid >> 7;
        for (int i = tid; i < NH * C; i += 1024) {
            int h = i >> 9, ci = i & (C - 1);
            buf[ci * 8 + h] = g_qw[(size_t)b * NH * C + i];
        }
        __syncthreads();

        int t = t0 + 2 * tl;
        const float2* xb = (const float2*)(x + (size_t)b * C * HW + t);
        const float2* pb = (const float2*)(g_poss + t);
        u64 a0[4], a1[4];
        #pragma unroll
        for (int i = 0; i < 4; i++) { a0[i] = 0ull; a1[i] = 0ull; }
        int ci0 = slab * 64;
        #pragma unroll 4
        for (int cc = 0; cc < 64; cc++) {
            int ci = ci0 + cc;
            float2 xv = xb[(size_t)ci * (HW / 2)];
            float2 pv = pb[(size_t)ci * (HW / 2)];
            float v0 = xv.x + pv.x, v1 = xv.y + pv.y;
            u64 s0 = pack2(v0, v0), s1 = pack2(v1, v1);
            const float4* wv = (const float4*)&buf[ci * 8];
            float4 w0 = wv[0], w1 = wv[1];
            u64 wp0 = pack2(w0.x, w0.y), wp1 = pack2(w0.z, w0.w);
            u64 wp2 = pack2(w1.x, w1.y), wp3 = pack2(w1.z, w1.w);
            fma2(a0[0], wp0, s0); fma2(a0[1], wp1, s0);
            fma2(a0[2], wp2, s0); fma2(a0[3], wp3, s0);
            fma2(a1[0], wp0, s1); fma2(a1[1], wp1, s1);
            fma2(a1[2], wp2, s1); fma2(a1[3], wp3, s1);
        }
        float* red = buf + 4096;                 // 8192 floats
        #pragma unroll
        for (int par = 0; par < 2; par++) {
            __syncthreads();
            #pragma unroll
            for (int hp = 0; hp < 4; hp++) {
                float2 f = unpack2(par == 0 ? a0[hp] : a1[hp]);
                red[tl * 64 + slab * 8 + hp * 2]     = f.x;
                red[tl * 64 + slab * 8 + hp * 2 + 1] = f.y;
            }
            __syncthreads();
            int tl2 = tid >> 3, h2 = tid & 7;    // 1024 (t,h) pairs
            float s = 0.0f;
            #pragma unroll
            for (int q = 0; q < 8; q++) s += red[tl2 * 64 + q * 8 + h2];
            g_p[((size_t)b * NH + h2) * T + t0 + 2 * tl2 + par + 1] = s;
        }
        __syncthreads();
    }
    gbar();

    // ---- Phase 5: softmax.  2 groups of 512 threads; 296 row-slots. --------
    {
        int grp  = warp >> 4;                    // 0 or 1
        int row  = bid * 2 + grp;
        int tid2 = tid & 511;
        int lw   = warp & 15;
        bool act = row < B * NH;
        const float* p = g_p + (size_t)row * T;
        float v0 = act ? p[tid2]        : -1e30f;
        float v1 = act ? p[tid2 + 512]  : -1e30f;
        float v2 = (act && tid2 == 0) ? p[1024] : -1e30f;
        float m = fmaxf(fmaxf(v0, v1), v2);
        #pragma unroll
        for (int o = 16; o; o >>= 1) m = fmaxf(m, __shfl_down_sync(0xffffffffu, m, o));
        if (lane == 0) buf[grp * 16 + lw] = m;
        __syncthreads();
        float M = buf[grp * 16];
        #pragma unroll
        for (int w = 1; w < 16; w++) M = fmaxf(M, buf[grp * 16 + w]);
        __syncthreads();
        float e0 = __expf(v0 - M), e1 = __expf(v1 - M);
        float e2 = (act && tid2 == 0) ? __expf(v2 - M) : 0.0f;
        float s = wred(e0 + e1 + e2);
        if (lane == 0) buf[grp * 16 + lw] = s;
        __syncthreads();
        float S = 0.0f;
        #pragma unroll
        for (int w = 0; w < 16; w++) S += buf[grp * 16 + w];
        float inv = 1.0f / S;
        if (act) {
            if (tid2 == 0) {
                g_p0[row] = e0 * inv;
                g_ps[(size_t)row * HW + 1023] = e2 * inv;   // t=1024
            } else {
                g_ps[(size_t)row * HW + tid2 - 1] = e0 * inv;
            }
            g_ps[(size_t)row * HW + tid2 + 511] = e1 * inv; // t=tid2+512
        }
        __syncthreads();
    }
    gbar();

    // ---- Phase 6: y = p . xf.  Warp owns 2 ci; FFMA2 over t-pairs. ---------
    {
        const int NIT = B * 8;               // (b, ci-group-of-64)
        int start = (int)(((long long)bid * NIT) / NB);
        int end   = (int)(((long long)(bid + 1) * NIT) / NB);
        int cur_b = -1;
        for (int it = start; it < end; it++) {
            int b = it >> 3, cig = it & 7;
            if (b != cur_b) {
                __syncthreads();
                const float4* src = (const float4*)(g_ps + (size_t)b * NH * HW);
                float4* dst = (float4*)buf;
                dst[tid] = src[tid];
                dst[tid + 1024] = src[tid + 1024];
                if (tid < NH) buf[8192 + tid] = g_p0[b * NH + tid];
                __syncthreads();
                cur_b = b;
            }
            int ci0 = cig * 64 + warp * 2;
            const float4* xr0 = (const float4*)(x + ((size_t)b * C + ci0) * HW);
            const float4* xr1 = xr0 + (HW / 4);
            const float4* pr0 = (const float4*)(g_poss + (size_t)ci0 * HW);
            const float4* pr1 = pr0 + (HW / 4);
            u64 acca[8], accc[8];
            #pragma unroll
            for (int h = 0; h < 8; h++) { acca[h] = 0ull; accc[h] = 0ull; }
            #pragma unroll
            for (int k = 0; k < 8; k++) {
                int i4 = lane + 32 * k;
                float4 xa = xr0[i4], pa = pr0[i4];
                float4 xc = xr1[i4], pc = pr1[i4];
                u64 va01 = add2(pack2(xa.x, xa.y), pack2(pa.x, pa.y));
                u64 va23 = add2(pack2(xa.z, xa.w), pack2(pa.z, pa.w));
                u64 vc01 = add2(pack2(xc.x, xc.y), pack2(pc.x, pc.y));
                u64 vc23 = add2(pack2(xc.z, xc.w), pack2(pc.z, pc.w));
                #pragma unroll
                for (int h = 0; h < 8; h++) {
                    float4 pv = ((const float4*)buf)[h * (HW / 4) + i4];
                    u64 p01 = pack2(pv.x, pv.y), p23 = pack2(pv.z, pv.w);
                    fma2(acca[h], p01, va01);
                    fma2(acca[h], p23, va23);
                    fma2(accc[h], p01, vc01);
                    fma2(accc[h], p23, vc23);
                }
            }
            float ra[8], rc[8];
            #pragma unroll
            for (int h = 0; h < 8; h++) {
                float2 fa = unpack2(acca[h]);
                float2 fc = unpack2(accc[h]);
                ra[h] = fa.x + fa.y;
                rc[h] = fc.x + fc.y;
            }
            if (lane == 0) {
                float va = g_x0[(size_t)b * C + ci0];
                float vc = g_x0[(size_t)b * C + ci0 + 1];
                #pragma unroll
                for (int h = 0; h < 8; h++) {
                    ra[h] += buf[8192 + h] * va;
                    rc[h] += buf[8192 + h] * vc;
                }
            }
            #pragma unroll
            for (int h = 0; h < 8; h++) {
                float r0 = wred(ra[h]);
                float r1 = wred(rc[h]);
                if (lane == 0) {
                    g_y[((size_t)b * NH + h) * C + ci0]     = r0;
                    g_y[((size_t)b * NH + h) * C + ci0 + 1] = r1;
                }
            }
        }
    }
    gbar();

    // ---- Phase 7: attn = b_v + W_v . y.  Warp per (c, b-group-of-8). -------
    for (int it = gw; it < C * 4; it += NW) {
        int c = it >> 2, bg = it & 3, h = c >> 6;
        const float4* w = (const float4*)(wqkv + (size_t)(2 * C + c) * C);
        float4 wr[4];
        #pragma unroll
        for (int k = 0; k < 4; k++) wr[k] = w[lane + 32 * k];
        float bv = bqkv[2 * C + c];
        #pragma unroll
        for (int j = 0; j < 8; j++) {
            int b = bg * 8 + j;
            const float4* y = (const float4*)(g_y + ((size_t)b * NH + h) * C);
            float acc = 0.0f;
            #pragma unroll
            for (int k = 0; k < 4; k++) {
                float4 d = y[lane + 32 * k];
                acc += wr[k].x * d.x + wr[k].y * d.y + wr[k].z * d.z + wr[k].w * d.w;
            }
            acc = wred(acc);
            if (lane == 0) g_a[b * C + c] = acc + bv;
        }
    }
    gbar();

    // ---- Phase 8: out = b_c + W_c . attn.  Warp per (o, b-group-of-8). -----
    for (int it = gw; it < C * 4; it += NW) {
        int o = it >> 2, bg = it & 3;
        const float4* w = (const float4*)(wc + (size_t)o * C);
        float4 wr[4];
        #pragma unroll
        for (int k = 0; k < 4; k++) wr[k] = w[lane + 32 * k];
        float bo = bc[o];
        #pragma unroll
        for (int j = 0; j < 8; j++) {
            int b = bg * 8 + j;
            const float4* a = (const float4*)(g_a + (size_t)b * C);
            float acc = 0.0f;
            #pragma unroll
            for (int k = 0; k < 4; k++) {
                float4 d = a[lane + 32 * k];
                acc += wr[k].x * d.x + wr[k].y * d.y + wr[k].z * d.z + wr[k].w * d.w;
            }
            acc = wred(acc);
            if (lane == 0) out[b * C + o] = acc + bo;
        }
    }
}

// ---------------------------------------------------------------------------
extern "C" void kernel_launch(void* const* d_in, const int* in_sizes, int n_in,
                              void* d_out, int out_size) {
    const float* x    = (const float*)d_in[0];
    const float* pos  = (const float*)d_in[1];
    const float* wqkv = (const float*)d_in[2];
    const float* bqkv = (const float*)d_in[3];
    const float* wc   = (const float*)d_in[4];
    const float* bc   = (const float*)d_in[5];
    float* out = (float*)d_out;

    int nsm = 0;
    cudaDeviceGetAttribute(&nsm, cudaDevAttrMultiProcessorCount, 0);
    if (nsm <= 0) nsm = 148;
    attn_pool_persistent<<<nsm, 1024>>>(x, pos, wqkv, bqkv, wc, bc, out);
}